// round 13
// baseline (speedup 1.0000x reference)
#include <cuda_runtime.h>
#include <cuda_fp16.h>
#include <mma.h>
#include <math.h>
#include <stdint.h>

using namespace nvcuda;

#define N_USERS_C 100000
#define N_ITEMS_C 50000
#define N_NODES_C 150000
#define D_C 64
#define NNZ_C 2400000
#define BATCH_C 2048
#define SCB 256
#define NBLK_SCAN ((N_NODES_C + SCB - 1) / SCB)   // 586

// Scratch buffers (allocation-free rule: device globals; zero-initialized at load)
__device__ float g_side[N_NODES_C * D_C];
__device__ float g_ego1[N_NODES_C * D_C];
__device__ float g_ego2[N_NODES_C * D_C];
__device__ uint2 g_egoh[N_NODES_C * 16];  // fp16 copy of current ego
__device__ int   g_cnt[N_NODES_C];        // invariant: zero at call entry/exit
__device__ int   g_wpos[N_NODES_C];
__device__ int   g_bsum[1024];
__device__ int2  g_epack[NNZ_C];          // packed (row18,col18,val16) by row

// ---------------------------------------------------------------------------
// pre: zero side accumulator + build fp16 copy of x (one streaming kernel)
// ---------------------------------------------------------------------------
__global__ void pre_kernel(float4* __restrict__ side,
                           const float4* __restrict__ x,
                           uint2* __restrict__ egoh, int n4) {
    int i = blockIdx.x * blockDim.x + threadIdx.x;
    if (i >= n4) return;
    side[i] = make_float4(0.f, 0.f, 0.f, 0.f);
    float4 v = x[i];
    __half2 a = __floats2half2_rn(v.x, v.y);
    __half2 b = __floats2half2_rn(v.z, v.w);
    uint2 o;
    o.x = *reinterpret_cast<unsigned*>(&a);
    o.y = *reinterpret_cast<unsigned*>(&b);
    egoh[i] = o;
}

// fp32 -> fp16 only (layer-2 conversion; side zeroing now fused into dense)
__global__ void f2h_kernel(const float4* __restrict__ in, uint2* __restrict__ out, int n4) {
    int i = blockIdx.x * blockDim.x + threadIdx.x;
    if (i >= n4) return;
    float4 v = in[i];
    __half2 a = __floats2half2_rn(v.x, v.y);
    __half2 b = __floats2half2_rn(v.z, v.w);
    uint2 o;
    o.x = *reinterpret_cast<unsigned*>(&a);
    o.y = *reinterpret_cast<unsigned*>(&b);
    out[i] = o;
}

// ---------------------------------------------------------------------------
// Histogram of row degrees (cnt is zero at entry by invariant)
// ---------------------------------------------------------------------------
__global__ void hist_kernel(const int* __restrict__ rows, int* __restrict__ cnt) {
    int e = blockIdx.x * blockDim.x + threadIdx.x;
    if (e < NNZ_C) atomicAdd(&cnt[rows[e]], 1);
}

// ---------------------------------------------------------------------------
// Hierarchical scan: per-block sums -> 1-block scan -> per-block final.
// scan_final also re-zeroes cnt (restores the invariant for the next call).
// ---------------------------------------------------------------------------
__global__ void blocksum_kernel(const int* __restrict__ cnt, int* __restrict__ bsum) {
    __shared__ int s[SCB];
    int i = blockIdx.x * SCB + threadIdx.x;
    s[threadIdx.x] = (i < N_NODES_C) ? cnt[i] : 0;
    __syncthreads();
#pragma unroll
    for (int o = SCB / 2; o > 0; o >>= 1) {
        if (threadIdx.x < o) s[threadIdx.x] += s[threadIdx.x + o];
        __syncthreads();
    }
    if (threadIdx.x == 0) bsum[blockIdx.x] = s[0];
}

__global__ __launch_bounds__(1024)
void scan_bsum_kernel(int* __restrict__ bsum) {
    __shared__ int s[1024];
    int tid = threadIdx.x;
    int v = (tid < NBLK_SCAN) ? bsum[tid] : 0;
    s[tid] = v;
    __syncthreads();
    for (int o = 1; o < 1024; o <<= 1) {
        int a = (tid >= o) ? s[tid - o] : 0;
        __syncthreads();
        s[tid] += a;
        __syncthreads();
    }
    if (tid < NBLK_SCAN) bsum[tid] = s[tid] - v;   // exclusive
}

__global__ void scan_final_kernel(int* __restrict__ cnt,
                                  const int* __restrict__ bsum,
                                  int* __restrict__ wpos) {
    __shared__ int s[SCB];
    int i = blockIdx.x * SCB + threadIdx.x;
    int v = (i < N_NODES_C) ? cnt[i] : 0;
    s[threadIdx.x] = v;
    __syncthreads();
    for (int o = 1; o < SCB; o <<= 1) {
        int a = (threadIdx.x >= o) ? s[threadIdx.x - o] : 0;
        __syncthreads();
        s[threadIdx.x] += a;
        __syncthreads();
    }
    if (i < N_NODES_C) {
        wpos[i] = bsum[blockIdx.x] + s[threadIdx.x] - v;
        cnt[i] = 0;   // restore invariant for next call / replay
    }
}

// ---------------------------------------------------------------------------
// Reorder into row-grouped packed int2: w0 = col | rowLow14<<18,
// w1 = rowHigh4 | val_fp16<<16
// ---------------------------------------------------------------------------
__global__ void reorder_kernel(const int* __restrict__ rows,
                               const int* __restrict__ cols,
                               const float* __restrict__ vals,
                               int* __restrict__ wpos,
                               int2* __restrict__ epack) {
    int e = blockIdx.x * blockDim.x + threadIdx.x;
    if (e >= NNZ_C) return;
    int r = rows[e];
    int p = atomicAdd(&wpos[r], 1);
    unsigned short hv = __half_as_ushort(__float2half_rn(vals[e]));
    int w0 = cols[e] | ((r & 0x3FFF) << 18);
    int w1 = (r >> 14) | ((int)hv << 16);
    epack[p] = make_int2(w0, w1);
}

// ---------------------------------------------------------------------------
// Segmented SpMM over row-sorted packed edges, fp16 gather (best config)
// ---------------------------------------------------------------------------
#define EPS_C 16
#define EPB_C 256

__device__ __forceinline__ void red_v4(float4* dst, float4 a) {
    asm volatile("red.global.add.v4.f32 [%0], {%1, %2, %3, %4};"
                 :: "l"(dst), "f"(a.x), "f"(a.y), "f"(a.z), "f"(a.w)
                 : "memory");
}

__global__ __launch_bounds__(256)
void seg_spmm_h_kernel(const int2* __restrict__ epack,
                       const uint2* __restrict__ egoh,
                       float4* __restrict__ side) {
    int tid  = threadIdx.x;
    int slot = tid >> 4;
    int lane = tid & 15;
    int half = (tid & 31) >= 16 ? 16 : 0;
    int e0 = blockIdx.x * EPB_C + slot * EPS_C;

    int2 ep = epack[e0 + lane];

    float4 acc = make_float4(0.f, 0.f, 0.f, 0.f);
    int cur = -1;

#pragma unroll
    for (int b = 0; b < 4; b++) {
        int rr[4]; float vv[4]; uint2 gh[4];
#pragma unroll
        for (int u = 0; u < 4; u++) {
            int src = half + b * 4 + u;
            int w0 = __shfl_sync(0xffffffffu, ep.x, src);
            int w1 = __shfl_sync(0xffffffffu, ep.y, src);
            int c  = w0 & 0x3FFFF;
            rr[u]  = ((w0 >> 18) & 0x3FFF) | ((w1 & 0xF) << 14);
            vv[u]  = __half2float(__ushort_as_half((unsigned short)((unsigned)w1 >> 16)));
            gh[u]  = egoh[c * 16 + lane];
        }
#pragma unroll
        for (int u = 0; u < 4; u++) {
            if (rr[u] != cur) {
                if (cur >= 0) red_v4(&side[cur * 16 + lane], acc);
                acc = make_float4(0.f, 0.f, 0.f, 0.f);
                cur = rr[u];
            }
            __half2 h01 = *reinterpret_cast<__half2*>(&gh[u].x);
            __half2 h23 = *reinterpret_cast<__half2*>(&gh[u].y);
            float2 f01 = __half22float2(h01);
            float2 f23 = __half22float2(h23);
            acc.x = fmaf(vv[u], f01.x, acc.x);
            acc.y = fmaf(vv[u], f01.y, acc.y);
            acc.z = fmaf(vv[u], f23.x, acc.z);
            acc.w = fmaf(vv[u], f23.y, acc.w);
        }
    }
    if (cur >= 0)
        red_v4(&side[cur * 16 + lane], acc);
}

// ---------------------------------------------------------------------------
// Dense layer via tensor cores (HMMA fp16 in / fp32 accumulate).
// Optionally zeroes side after reading it (prepares next layer's accumulator).
// ---------------------------------------------------------------------------
#define TM_C 64
#define KDIM_C 128
#define LDA_C 136
#define LDB_C 72

__global__ __launch_bounds__(128)
void dense_kernel(float4* __restrict__ side,
                  const float4* __restrict__ ego,
                  const float4* __restrict__ Wg, const float* __restrict__ bg,
                  const float4* __restrict__ Wb, const float* __restrict__ bb,
                  float4* __restrict__ out, int numTiles, int zeroSide) {
    extern __shared__ char smem[];
    __half* A   = (__half*)smem;                               // [64][136] halves
    __half* B   = (__half*)(smem + TM_C * LDA_C * 2);          // [128][72] halves
    float*  C   = (float*)(smem + TM_C * LDA_C * 2 + KDIM_C * LDB_C * 2);  // [64][64]
    float*  bsum = C + TM_C * D_C;                             // [64]

    int tid = threadIdx.x;
    int wid = tid >> 5;

#pragma unroll
    for (int i = 0; i < 16; i++) {
        int f = tid + i * 128;
        int k = f >> 4, c4 = f & 15;
        float4 w = (k < 64) ? Wg[k * 16 + c4] : Wb[(k - 64) * 16 + c4];
        __half2* dst = (__half2*)&B[k * LDB_C + c4 * 4];
        dst[0] = __floats2half2_rn(w.x, w.y);
        dst[1] = __floats2half2_rn(w.z, w.w);
    }
    if (tid < 64) bsum[tid] = bg[tid] + bb[tid];
    __syncthreads();

    for (int tile = blockIdx.x; tile < numTiles; tile += gridDim.x) {
        int row0 = tile * TM_C;

#pragma unroll
        for (int i = 0; i < 8; i++) {
            int f = tid + i * 128;
            int r = f >> 4, k4 = f & 15;
            float4 s  = make_float4(0.f, 0.f, 0.f, 0.f);
            float4 pr = make_float4(0.f, 0.f, 0.f, 0.f);
            int grow = row0 + r;
            if (grow < N_NODES_C) {
                s = side[grow * 16 + k4];
                float4 e = ego[grow * 16 + k4];
                pr = make_float4(s.x * e.x, s.y * e.y, s.z * e.z, s.w * e.w);
                if (zeroSide)
                    side[grow * 16 + k4] = make_float4(0.f, 0.f, 0.f, 0.f);
            }
            __half2* dS = (__half2*)&A[r * LDA_C + k4 * 4];
            dS[0] = __floats2half2_rn(s.x, s.y);
            dS[1] = __floats2half2_rn(s.z, s.w);
            __half2* dP = (__half2*)&A[r * LDA_C + 64 + k4 * 4];
            dP[0] = __floats2half2_rn(pr.x, pr.y);
            dP[1] = __floats2half2_rn(pr.z, pr.w);
        }
        __syncthreads();

        {
            wmma::fragment<wmma::accumulator, 16, 16, 16, float> c_frag[4];
#pragma unroll
            for (int n = 0; n < 4; n++) wmma::fill_fragment(c_frag[n], 0.f);
#pragma unroll
            for (int k = 0; k < KDIM_C / 16; k++) {
                wmma::fragment<wmma::matrix_a, 16, 16, 16, __half, wmma::row_major> a_frag;
                wmma::load_matrix_sync(a_frag, &A[(16 * wid) * LDA_C + k * 16], LDA_C);
#pragma unroll
                for (int n = 0; n < 4; n++) {
                    wmma::fragment<wmma::matrix_b, 16, 16, 16, __half, wmma::row_major> b_frag;
                    wmma::load_matrix_sync(b_frag, &B[(k * 16) * LDB_C + n * 16], LDB_C);
                    wmma::mma_sync(c_frag[n], a_frag, b_frag, c_frag[n]);
                }
            }
#pragma unroll
            for (int n = 0; n < 4; n++)
                wmma::store_matrix_sync(&C[(16 * wid) * D_C + n * 16], c_frag[n],
                                        D_C, wmma::mem_row_major);
        }
        __syncthreads();

        {
            int row = tid >> 1;
            int hs  = tid & 1;
            const float* Crow = C + row * D_C + hs * 32;
            const float* brow = bsum + hs * 32;
            float vbuf[32];
            float ss = 0.f;
#pragma unroll
            for (int j = 0; j < 32; j++) {
                float v = Crow[j] + brow[j];
                v = (v > 0.f) ? v : 0.2f * v;
                vbuf[j] = v;
                ss += v * v;
            }
            ss += __shfl_xor_sync(0xffffffffu, ss, 1);
            float scl = 1.0f / fmaxf(sqrtf(ss), 1e-12f);
            int grow = row0 + row;
            if (grow < N_NODES_C) {
#pragma unroll
                for (int j = 0; j < 8; j++)
                    out[grow * 16 + hs * 8 + j] =
                        make_float4(vbuf[4 * j] * scl, vbuf[4 * j + 1] * scl,
                                    vbuf[4 * j + 2] * scl, vbuf[4 * j + 3] * scl);
            }
        }
        __syncthreads();
    }
}

// ---------------------------------------------------------------------------
// gamma[b] = sum over 3 embeddings of dot(emb[u], emb[N_USERS+item])
// ---------------------------------------------------------------------------
__global__ void gamma_kernel(const float* __restrict__ x,
                             const int* __restrict__ users,
                             const int* __restrict__ items,
                             float* __restrict__ out) {
    int b = blockIdx.x * 8 + (threadIdx.x >> 5);
    if (b >= BATCH_C) return;
    int lane = threadIdx.x & 31;
    int u  = users[b];
    int it = N_USERS_C + items[b];
    long long ub = (long long)u * D_C, ib = (long long)it * D_C;
    float acc = 0.f;
    acc += x[ub + lane]      * x[ib + lane];
    acc += x[ub + 32 + lane] * x[ib + 32 + lane];
    acc += g_ego1[ub + lane]      * g_ego1[ib + lane];
    acc += g_ego1[ub + 32 + lane] * g_ego1[ib + 32 + lane];
    acc += g_ego2[ub + lane]      * g_ego2[ib + lane];
    acc += g_ego2[ub + 32 + lane] * g_ego2[ib + 32 + lane];
#pragma unroll
    for (int o = 16; o > 0; o >>= 1)
        acc += __shfl_xor_sync(0xffffffffu, acc, o);
    if (lane == 0) out[b] = acc;
}

// ---------------------------------------------------------------------------
extern "C" void kernel_launch(void* const* d_in, const int* in_sizes, int n_in,
                              void* d_out, int out_size) {
    const int*   rows = (const int*)d_in[0];
    const int*   cols = (const int*)d_in[1];
    const float* vals = (const float*)d_in[2];
    const float* x    = (const float*)d_in[3];

    const float *Wg0, *bg0, *Wb0, *bb0, *Wg1, *bg1, *Wb1, *bb1;
    const int *users, *items;
    if (in_sizes[4] == BATCH_C) {
        users = (const int*)d_in[4];
        items = (const int*)d_in[5];
        Wg0 = (const float*)d_in[6];  bg0 = (const float*)d_in[7];
        Wb0 = (const float*)d_in[8];  bb0 = (const float*)d_in[9];
        Wg1 = (const float*)d_in[10]; bg1 = (const float*)d_in[11];
        Wb1 = (const float*)d_in[12]; bb1 = (const float*)d_in[13];
    } else {
        Wg0 = (const float*)d_in[4];  bg0 = (const float*)d_in[5];
        Wb0 = (const float*)d_in[6];  bb0 = (const float*)d_in[7];
        Wg1 = (const float*)d_in[8];  bg1 = (const float*)d_in[9];
        Wb1 = (const float*)d_in[10]; bb1 = (const float*)d_in[11];
        users = (const int*)d_in[12];
        items = (const int*)d_in[13];
    }

    float *side, *ego1, *ego2;
    uint2 *egoh;
    int *cnt, *wpos, *bsum;
    int2 *epack;
    cudaGetSymbolAddress((void**)&side,  g_side);
    cudaGetSymbolAddress((void**)&ego1,  g_ego1);
    cudaGetSymbolAddress((void**)&ego2,  g_ego2);
    cudaGetSymbolAddress((void**)&egoh,  g_egoh);
    cudaGetSymbolAddress((void**)&cnt,   g_cnt);
    cudaGetSymbolAddress((void**)&wpos,  g_wpos);
    cudaGetSymbolAddress((void**)&bsum,  g_bsum);
    cudaGetSymbolAddress((void**)&epack, g_epack);

    int denseSmem = TM_C * LDA_C * 2 + KDIM_C * LDB_C * 2 + TM_C * D_C * 4 + 64 * 4;
    cudaFuncSetAttribute(dense_kernel, cudaFuncAttributeMaxDynamicSharedMemorySize, denseSmem);

    int numTiles   = (N_NODES_C + TM_C - 1) / TM_C;       // 2344
    int edgeBlocks = (NNZ_C + 255) / 256;                 // 9375
    int z4 = N_NODES_C * 16;
    int zeroBlocks = (z4 + 255) / 256;                    // 9375
    int spmmBlocks = NNZ_C / EPB_C;                       // 9375

    // 0: side zero + fp16 copy of x   1-4: build (cnt is 0 by invariant)
    pre_kernel<<<zeroBlocks, 256>>>((float4*)side, (const float4*)x, egoh, z4);
    hist_kernel<<<edgeBlocks, 256>>>(rows, cnt);
    blocksum_kernel<<<NBLK_SCAN, SCB>>>(cnt, bsum);
    scan_bsum_kernel<<<1, 1024>>>(bsum);
    scan_final_kernel<<<NBLK_SCAN, SCB>>>(cnt, bsum, wpos);   // also re-zeroes cnt
    reorder_kernel<<<edgeBlocks, 256>>>(rows, cols, vals, wpos, epack);
    // Layer 1 (dense re-zeroes side for layer 2)
    seg_spmm_h_kernel<<<spmmBlocks, 256>>>(epack, egoh, (float4*)side);
    dense_kernel<<<592, 128, denseSmem>>>((float4*)side, (const float4*)x,
                                          (const float4*)Wg0, bg0,
                                          (const float4*)Wb0, bb0,
                                          (float4*)ego1, numTiles, 1);
    // Layer 2
    f2h_kernel<<<zeroBlocks, 256>>>((const float4*)ego1, egoh, z4);
    seg_spmm_h_kernel<<<spmmBlocks, 256>>>(epack, egoh, (float4*)side);
    dense_kernel<<<592, 128, denseSmem>>>((float4*)side, (const float4*)ego1,
                                          (const float4*)Wg1, bg1,
                                          (const float4*)Wb1, bb1,
                                          (float4*)ego2, numTiles, 0);
    // Final BPR scores
    gamma_kernel<<<BATCH_C / 8, 256>>>(x, users, items, (float*)d_out);
}

// round 14
// speedup vs baseline: 1.8862x; 1.8862x over previous
#include <cuda_runtime.h>
#include <cuda_fp16.h>
#include <mma.h>
#include <math.h>
#include <stdint.h>

using namespace nvcuda;

#define N_USERS_C 100000
#define N_ITEMS_C 50000
#define N_NODES_C 150000
#define D_C 64
#define NNZ_C 2400000
#define BATCH_C 2048
#define SCB 256
#define NBLK_SCAN ((N_NODES_C + SCB - 1) / SCB)   // 586

// Scratch buffers (allocation-free rule: device globals)
__device__ float g_side[N_NODES_C * D_C];
__device__ float g_ego1[N_NODES_C * D_C];
__device__ float g_ego2[N_NODES_C * D_C];
__device__ uint2 g_egoh[N_NODES_C * 16];  // fp16 copy of current ego
__device__ int   g_cnt[N_NODES_C];
__device__ int   g_wpos[N_NODES_C];
__device__ int   g_bsum[1024];
__device__ int2  g_epack[NNZ_C];          // packed (row18,col18,val16) by row

// ---------------------------------------------------------------------------
// pre: zero cnt + side accumulator (one streaming kernel)
// ---------------------------------------------------------------------------
__global__ void pre_kernel(int* __restrict__ cnt, float4* __restrict__ side, int n4) {
    int i = blockIdx.x * blockDim.x + threadIdx.x;
    if (i < n4) side[i] = make_float4(0.f, 0.f, 0.f, 0.f);
    if (i < N_NODES_C) cnt[i] = 0;
}

// ---------------------------------------------------------------------------
// fp32 -> fp16 conversion (streaming); variant with side zeroing fused.
// NOTE: f2h_zero runs IMMEDIATELY before the layer-2 SpMM — the side zeroing
// doubles as an L2 warm/prefetch of the RED target. Placement is load-bearing.
// ---------------------------------------------------------------------------
__global__ void f2h_kernel(const float4* __restrict__ in, uint2* __restrict__ out, int n4) {
    int i = blockIdx.x * blockDim.x + threadIdx.x;
    if (i >= n4) return;
    float4 v = in[i];
    __half2 a = __floats2half2_rn(v.x, v.y);
    __half2 b = __floats2half2_rn(v.z, v.w);
    uint2 o;
    o.x = *reinterpret_cast<unsigned*>(&a);
    o.y = *reinterpret_cast<unsigned*>(&b);
    out[i] = o;
}

__global__ void f2h_zero_kernel(const float4* __restrict__ in, uint2* __restrict__ out,
                                float4* __restrict__ side, int n4) {
    int i = blockIdx.x * blockDim.x + threadIdx.x;
    if (i >= n4) return;
    float4 v = in[i];
    __half2 a = __floats2half2_rn(v.x, v.y);
    __half2 b = __floats2half2_rn(v.z, v.w);
    uint2 o;
    o.x = *reinterpret_cast<unsigned*>(&a);
    o.y = *reinterpret_cast<unsigned*>(&b);
    out[i] = o;
    side[i] = make_float4(0.f, 0.f, 0.f, 0.f);
}

// ---------------------------------------------------------------------------
// Histogram of row degrees
// ---------------------------------------------------------------------------
__global__ void hist_kernel(const int* __restrict__ rows, int* __restrict__ cnt) {
    int e = blockIdx.x * blockDim.x + threadIdx.x;
    if (e < NNZ_C) atomicAdd(&cnt[rows[e]], 1);
}

// ---------------------------------------------------------------------------
// Hierarchical scan: per-block sums -> 1-block scan -> per-block final
// ---------------------------------------------------------------------------
__global__ void blocksum_kernel(const int* __restrict__ cnt, int* __restrict__ bsum) {
    __shared__ int s[SCB];
    int i = blockIdx.x * SCB + threadIdx.x;
    s[threadIdx.x] = (i < N_NODES_C) ? cnt[i] : 0;
    __syncthreads();
#pragma unroll
    for (int o = SCB / 2; o > 0; o >>= 1) {
        if (threadIdx.x < o) s[threadIdx.x] += s[threadIdx.x + o];
        __syncthreads();
    }
    if (threadIdx.x == 0) bsum[blockIdx.x] = s[0];
}

__global__ __launch_bounds__(1024)
void scan_bsum_kernel(int* __restrict__ bsum) {
    __shared__ int s[1024];
    int tid = threadIdx.x;
    int v = (tid < NBLK_SCAN) ? bsum[tid] : 0;
    s[tid] = v;
    __syncthreads();
    for (int o = 1; o < 1024; o <<= 1) {
        int a = (tid >= o) ? s[tid - o] : 0;
        __syncthreads();
        s[tid] += a;
        __syncthreads();
    }
    if (tid < NBLK_SCAN) bsum[tid] = s[tid] - v;   // exclusive
}

__global__ void scan_final_kernel(const int* __restrict__ cnt,
                                  const int* __restrict__ bsum,
                                  int* __restrict__ wpos) {
    __shared__ int s[SCB];
    int i = blockIdx.x * SCB + threadIdx.x;
    int v = (i < N_NODES_C) ? cnt[i] : 0;
    s[threadIdx.x] = v;
    __syncthreads();
    for (int o = 1; o < SCB; o <<= 1) {
        int a = (threadIdx.x >= o) ? s[threadIdx.x - o] : 0;
        __syncthreads();
        s[threadIdx.x] += a;
        __syncthreads();
    }
    if (i < N_NODES_C) wpos[i] = bsum[blockIdx.x] + s[threadIdx.x] - v;
}

// ---------------------------------------------------------------------------
// Reorder into row-grouped packed int2: w0 = col | rowLow14<<18,
// w1 = rowHigh4 | val_fp16<<16
// ---------------------------------------------------------------------------
__global__ void reorder_kernel(const int* __restrict__ rows,
                               const int* __restrict__ cols,
                               const float* __restrict__ vals,
                               int* __restrict__ wpos,
                               int2* __restrict__ epack) {
    int e = blockIdx.x * blockDim.x + threadIdx.x;
    if (e >= NNZ_C) return;
    int r = rows[e];
    int p = atomicAdd(&wpos[r], 1);
    unsigned short hv = __half_as_ushort(__float2half_rn(vals[e]));
    int w0 = cols[e] | ((r & 0x3FFF) << 18);
    int w1 = (r >> 14) | ((int)hv << 16);
    epack[p] = make_int2(w0, w1);
}

// ---------------------------------------------------------------------------
// Segmented SpMM over row-sorted packed edges, fp16 gather (best config)
// ---------------------------------------------------------------------------
#define EPS_C 16
#define EPB_C 256

__device__ __forceinline__ void red_v4(float4* dst, float4 a) {
    asm volatile("red.global.add.v4.f32 [%0], {%1, %2, %3, %4};"
                 :: "l"(dst), "f"(a.x), "f"(a.y), "f"(a.z), "f"(a.w)
                 : "memory");
}

__global__ __launch_bounds__(256)
void seg_spmm_h_kernel(const int2* __restrict__ epack,
                       const uint2* __restrict__ egoh,
                       float4* __restrict__ side) {
    int tid  = threadIdx.x;
    int slot = tid >> 4;
    int lane = tid & 15;
    int half = (tid & 31) >= 16 ? 16 : 0;
    int e0 = blockIdx.x * EPB_C + slot * EPS_C;

    int2 ep = epack[e0 + lane];

    float4 acc = make_float4(0.f, 0.f, 0.f, 0.f);
    int cur = -1;

#pragma unroll
    for (int b = 0; b < 4; b++) {
        int rr[4]; float vv[4]; uint2 gh[4];
#pragma unroll
        for (int u = 0; u < 4; u++) {
            int src = half + b * 4 + u;
            int w0 = __shfl_sync(0xffffffffu, ep.x, src);
            int w1 = __shfl_sync(0xffffffffu, ep.y, src);
            int c  = w0 & 0x3FFFF;
            rr[u]  = ((w0 >> 18) & 0x3FFF) | ((w1 & 0xF) << 14);
            vv[u]  = __half2float(__ushort_as_half((unsigned short)((unsigned)w1 >> 16)));
            gh[u]  = egoh[c * 16 + lane];
        }
#pragma unroll
        for (int u = 0; u < 4; u++) {
            if (rr[u] != cur) {
                if (cur >= 0) red_v4(&side[cur * 16 + lane], acc);
                acc = make_float4(0.f, 0.f, 0.f, 0.f);
                cur = rr[u];
            }
            __half2 h01 = *reinterpret_cast<__half2*>(&gh[u].x);
            __half2 h23 = *reinterpret_cast<__half2*>(&gh[u].y);
            float2 f01 = __half22float2(h01);
            float2 f23 = __half22float2(h23);
            acc.x = fmaf(vv[u], f01.x, acc.x);
            acc.y = fmaf(vv[u], f01.y, acc.y);
            acc.z = fmaf(vv[u], f23.x, acc.z);
            acc.w = fmaf(vv[u], f23.y, acc.w);
        }
    }
    if (cur >= 0)
        red_v4(&side[cur * 16 + lane], acc);
}

// ---------------------------------------------------------------------------
// Dense layer via tensor cores (HMMA fp16 in / fp32 accumulate):
// out = l2norm(leaky_relu(side@Wg + (ego*side)@Wb + bg + bb))
// ---------------------------------------------------------------------------
#define TM_C 64
#define KDIM_C 128
#define LDA_C 136
#define LDB_C 72

__global__ __launch_bounds__(128)
void dense_kernel(const float4* __restrict__ side,
                  const float4* __restrict__ ego,
                  const float4* __restrict__ Wg, const float* __restrict__ bg,
                  const float4* __restrict__ Wb, const float* __restrict__ bb,
                  float4* __restrict__ out, int numTiles) {
    extern __shared__ char smem[];
    __half* A   = (__half*)smem;                               // [64][136] halves
    __half* B   = (__half*)(smem + TM_C * LDA_C * 2);          // [128][72] halves
    float*  C   = (float*)(smem + TM_C * LDA_C * 2 + KDIM_C * LDB_C * 2);  // [64][64]
    float*  bsum = C + TM_C * D_C;                             // [64]

    int tid = threadIdx.x;
    int wid = tid >> 5;

#pragma unroll
    for (int i = 0; i < 16; i++) {
        int f = tid + i * 128;
        int k = f >> 4, c4 = f & 15;
        float4 w = (k < 64) ? Wg[k * 16 + c4] : Wb[(k - 64) * 16 + c4];
        __half2* dst = (__half2*)&B[k * LDB_C + c4 * 4];
        dst[0] = __floats2half2_rn(w.x, w.y);
        dst[1] = __floats2half2_rn(w.z, w.w);
    }
    if (tid < 64) bsum[tid] = bg[tid] + bb[tid];
    __syncthreads();

    for (int tile = blockIdx.x; tile < numTiles; tile += gridDim.x) {
        int row0 = tile * TM_C;

#pragma unroll
        for (int i = 0; i < 8; i++) {
            int f = tid + i * 128;
            int r = f >> 4, k4 = f & 15;
            float4 s  = make_float4(0.f, 0.f, 0.f, 0.f);
            float4 pr = make_float4(0.f, 0.f, 0.f, 0.f);
            int grow = row0 + r;
            if (grow < N_NODES_C) {
                s = side[grow * 16 + k4];
                float4 e = ego[grow * 16 + k4];
                pr = make_float4(s.x * e.x, s.y * e.y, s.z * e.z, s.w * e.w);
            }
            __half2* dS = (__half2*)&A[r * LDA_C + k4 * 4];
            dS[0] = __floats2half2_rn(s.x, s.y);
            dS[1] = __floats2half2_rn(s.z, s.w);
            __half2* dP = (__half2*)&A[r * LDA_C + 64 + k4 * 4];
            dP[0] = __floats2half2_rn(pr.x, pr.y);
            dP[1] = __floats2half2_rn(pr.z, pr.w);
        }
        __syncthreads();

        {
            wmma::fragment<wmma::accumulator, 16, 16, 16, float> c_frag[4];
#pragma unroll
            for (int n = 0; n < 4; n++) wmma::fill_fragment(c_frag[n], 0.f);
#pragma unroll
            for (int k = 0; k < KDIM_C / 16; k++) {
                wmma::fragment<wmma::matrix_a, 16, 16, 16, __half, wmma::row_major> a_frag;
                wmma::load_matrix_sync(a_frag, &A[(16 * wid) * LDA_C + k * 16], LDA_C);
#pragma unroll
                for (int n = 0; n < 4; n++) {
                    wmma::fragment<wmma::matrix_b, 16, 16, 16, __half, wmma::row_major> b_frag;
                    wmma::load_matrix_sync(b_frag, &B[(k * 16) * LDB_C + n * 16], LDB_C);
                    wmma::mma_sync(c_frag[n], a_frag, b_frag, c_frag[n]);
                }
            }
#pragma unroll
            for (int n = 0; n < 4; n++)
                wmma::store_matrix_sync(&C[(16 * wid) * D_C + n * 16], c_frag[n],
                                        D_C, wmma::mem_row_major);
        }
        __syncthreads();

        {
            int row = tid >> 1;
            int hs  = tid & 1;
            const float* Crow = C + row * D_C + hs * 32;
            const float* brow = bsum + hs * 32;
            float vbuf[32];
            float ss = 0.f;
#pragma unroll
            for (int j = 0; j < 32; j++) {
                float v = Crow[j] + brow[j];
                v = (v > 0.f) ? v : 0.2f * v;
                vbuf[j] = v;
                ss += v * v;
            }
            ss += __shfl_xor_sync(0xffffffffu, ss, 1);
            float scl = 1.0f / fmaxf(sqrtf(ss), 1e-12f);
            int grow = row0 + row;
            if (grow < N_NODES_C) {
#pragma unroll
                for (int j = 0; j < 8; j++)
                    out[grow * 16 + hs * 8 + j] =
                        make_float4(vbuf[4 * j] * scl, vbuf[4 * j + 1] * scl,
                                    vbuf[4 * j + 2] * scl, vbuf[4 * j + 3] * scl);
            }
        }
        __syncthreads();
    }
}

// ---------------------------------------------------------------------------
// gamma[b] = sum over 3 embeddings of dot(emb[u], emb[N_USERS+item])
// ---------------------------------------------------------------------------
__global__ void gamma_kernel(const float* __restrict__ x,
                             const int* __restrict__ users,
                             const int* __restrict__ items,
                             float* __restrict__ out) {
    int b = blockIdx.x * 8 + (threadIdx.x >> 5);
    if (b >= BATCH_C) return;
    int lane = threadIdx.x & 31;
    int u  = users[b];
    int it = N_USERS_C + items[b];
    long long ub = (long long)u * D_C, ib = (long long)it * D_C;
    float acc = 0.f;
    acc += x[ub + lane]      * x[ib + lane];
    acc += x[ub + 32 + lane] * x[ib + 32 + lane];
    acc += g_ego1[ub + lane]      * g_ego1[ib + lane];
    acc += g_ego1[ub + 32 + lane] * g_ego1[ib + 32 + lane];
    acc += g_ego2[ub + lane]      * g_ego2[ib + lane];
    acc += g_ego2[ub + 32 + lane] * g_ego2[ib + 32 + lane];
#pragma unroll
    for (int o = 16; o > 0; o >>= 1)
        acc += __shfl_xor_sync(0xffffffffu, acc, o);
    if (lane == 0) out[b] = acc;
}

// ---------------------------------------------------------------------------
extern "C" void kernel_launch(void* const* d_in, const int* in_sizes, int n_in,
                              void* d_out, int out_size) {
    const int*   rows = (const int*)d_in[0];
    const int*   cols = (const int*)d_in[1];
    const float* vals = (const float*)d_in[2];
    const float* x    = (const float*)d_in[3];

    const float *Wg0, *bg0, *Wb0, *bb0, *Wg1, *bg1, *Wb1, *bb1;
    const int *users, *items;
    if (in_sizes[4] == BATCH_C) {
        users = (const int*)d_in[4];
        items = (const int*)d_in[5];
        Wg0 = (const float*)d_in[6];  bg0 = (const float*)d_in[7];
        Wb0 = (const float*)d_in[8];  bb0 = (const float*)d_in[9];
        Wg1 = (const float*)d_in[10]; bg1 = (const float*)d_in[11];
        Wb1 = (const float*)d_in[12]; bb1 = (const float*)d_in[13];
    } else {
        Wg0 = (const float*)d_in[4];  bg0 = (const float*)d_in[5];
        Wb0 = (const float*)d_in[6];  bb0 = (const float*)d_in[7];
        Wg1 = (const float*)d_in[8];  bg1 = (const float*)d_in[9];
        Wb1 = (const float*)d_in[10]; bb1 = (const float*)d_in[11];
        users = (const int*)d_in[12];
        items = (const int*)d_in[13];
    }

    float *side, *ego1, *ego2;
    uint2 *egoh;
    int *cnt, *wpos, *bsum;
    int2 *epack;
    cudaGetSymbolAddress((void**)&side,  g_side);
    cudaGetSymbolAddress((void**)&ego1,  g_ego1);
    cudaGetSymbolAddress((void**)&ego2,  g_ego2);
    cudaGetSymbolAddress((void**)&egoh,  g_egoh);
    cudaGetSymbolAddress((void**)&cnt,   g_cnt);
    cudaGetSymbolAddress((void**)&wpos,  g_wpos);
    cudaGetSymbolAddress((void**)&bsum,  g_bsum);
    cudaGetSymbolAddress((void**)&epack, g_epack);

    int denseSmem = TM_C * LDA_C * 2 + KDIM_C * LDB_C * 2 + TM_C * D_C * 4 + 64 * 4;
    cudaFuncSetAttribute(dense_kernel, cudaFuncAttributeMaxDynamicSharedMemorySize, denseSmem);

    int numTiles   = (N_NODES_C + TM_C - 1) / TM_C;       // 2344
    int edgeBlocks = (NNZ_C + 255) / 256;                 // 9375
    int z4 = N_NODES_C * 16;
    int zeroBlocks = (z4 + 255) / 256;                    // 9375
    int spmmBlocks = NNZ_C / EPB_C;                       // 9375

    // 0: zero cnt + side     1: fp16 copy of x
    pre_kernel<<<zeroBlocks, 256>>>(cnt, (float4*)side, z4);
    f2h_kernel<<<zeroBlocks, 256>>>((const float4*)x, egoh, z4);
    // 2-5: build row-grouped packed edge list (hierarchical scan)
    hist_kernel<<<edgeBlocks, 256>>>(rows, cnt);
    blocksum_kernel<<<NBLK_SCAN, SCB>>>(cnt, bsum);
    scan_bsum_kernel<<<1, 1024>>>(bsum);
    scan_final_kernel<<<NBLK_SCAN, SCB>>>(cnt, bsum, wpos);
    reorder_kernel<<<edgeBlocks, 256>>>(rows, cols, vals, wpos, epack);
    // Layer 1
    seg_spmm_h_kernel<<<spmmBlocks, 256>>>(epack, egoh, (float4*)side);
    dense_kernel<<<592, 128, denseSmem>>>((const float4*)side, (const float4*)x,
                                          (const float4*)Wg0, bg0,
                                          (const float4*)Wb0, bb0,
                                          (float4*)ego1, numTiles);
    // Layer 2 (f2h_zero immediately before spmm2: side zeroing = L2 warm)
    f2h_zero_kernel<<<zeroBlocks, 256>>>((const float4*)ego1, egoh, (float4*)side, z4);
    seg_spmm_h_kernel<<<spmmBlocks, 256>>>(epack, egoh, (float4*)side);
    dense_kernel<<<592, 128, denseSmem>>>((const float4*)side, (const float4*)ego1,
                                          (const float4*)Wg1, bg1,
                                          (const float4*)Wb1, bb1,
                                          (float4*)ego2, numTiles);
    // Final BPR scores
    gamma_kernel<<<BATCH_C / 8, 256>>>(x, users, items, (float*)d_out);
}

// round 15
// speedup vs baseline: 1.9020x; 1.0084x over previous
#include <cuda_runtime.h>
#include <cuda_fp16.h>
#include <mma.h>
#include <math.h>
#include <stdint.h>

using namespace nvcuda;

#define N_USERS_C 100000
#define N_ITEMS_C 50000
#define N_NODES_C 150000
#define D_C 64
#define NNZ_C 2400000
#define BATCH_C 2048
#define SCB 256
#define NBLK_SCAN ((N_NODES_C + SCB - 1) / SCB)   // 586

// Scratch buffers (allocation-free rule: device globals)
__device__ float g_side[N_NODES_C * D_C];
__device__ float g_ego1[N_NODES_C * D_C];
__device__ float g_ego2[N_NODES_C * D_C];
__device__ uint2 g_egoh[N_NODES_C * 16];  // fp16 copy of current ego
__device__ int   g_cnt[N_NODES_C];
__device__ int   g_wpos[N_NODES_C];
__device__ int   g_bsum[1024];
__device__ int2  g_epack[NNZ_C];          // packed (row18,col18,val16) by row

// ---------------------------------------------------------------------------
// zero cnt only (side zeroing moved to just-before-SpMM, see f2h_zero note)
// ---------------------------------------------------------------------------
__global__ void zero_cnt_kernel(int* __restrict__ cnt) {
    int i = blockIdx.x * blockDim.x + threadIdx.x;
    if (i < N_NODES_C) cnt[i] = 0;
}

// ---------------------------------------------------------------------------
// fp32 -> fp16 conversion with side zeroing fused.
// NOTE: f2h_zero runs IMMEDIATELY before each SpMM — writing egoh and zeroing
// side leaves BOTH the gather target and the RED target L2-resident when the
// SpMM starts. This placement is load-bearing (R13 regression: +204us when
// violated for layer 2; this round applies the same structure to layer 1).
// ---------------------------------------------------------------------------
__global__ void f2h_zero_kernel(const float4* __restrict__ in, uint2* __restrict__ out,
                                float4* __restrict__ side, int n4) {
    int i = blockIdx.x * blockDim.x + threadIdx.x;
    if (i >= n4) return;
    float4 v = in[i];
    __half2 a = __floats2half2_rn(v.x, v.y);
    __half2 b = __floats2half2_rn(v.z, v.w);
    uint2 o;
    o.x = *reinterpret_cast<unsigned*>(&a);
    o.y = *reinterpret_cast<unsigned*>(&b);
    out[i] = o;
    side[i] = make_float4(0.f, 0.f, 0.f, 0.f);
}

// ---------------------------------------------------------------------------
// Histogram of row degrees
// ---------------------------------------------------------------------------
__global__ void hist_kernel(const int* __restrict__ rows, int* __restrict__ cnt) {
    int e = blockIdx.x * blockDim.x + threadIdx.x;
    if (e < NNZ_C) atomicAdd(&cnt[rows[e]], 1);
}

// ---------------------------------------------------------------------------
// Hierarchical scan: per-block sums -> 1-block scan -> per-block final
// ---------------------------------------------------------------------------
__global__ void blocksum_kernel(const int* __restrict__ cnt, int* __restrict__ bsum) {
    __shared__ int s[SCB];
    int i = blockIdx.x * SCB + threadIdx.x;
    s[threadIdx.x] = (i < N_NODES_C) ? cnt[i] : 0;
    __syncthreads();
#pragma unroll
    for (int o = SCB / 2; o > 0; o >>= 1) {
        if (threadIdx.x < o) s[threadIdx.x] += s[threadIdx.x + o];
        __syncthreads();
    }
    if (threadIdx.x == 0) bsum[blockIdx.x] = s[0];
}

__global__ __launch_bounds__(1024)
void scan_bsum_kernel(int* __restrict__ bsum) {
    __shared__ int s[1024];
    int tid = threadIdx.x;
    int v = (tid < NBLK_SCAN) ? bsum[tid] : 0;
    s[tid] = v;
    __syncthreads();
    for (int o = 1; o < 1024; o <<= 1) {
        int a = (tid >= o) ? s[tid - o] : 0;
        __syncthreads();
        s[tid] += a;
        __syncthreads();
    }
    if (tid < NBLK_SCAN) bsum[tid] = s[tid] - v;   // exclusive
}

__global__ void scan_final_kernel(const int* __restrict__ cnt,
                                  const int* __restrict__ bsum,
                                  int* __restrict__ wpos) {
    __shared__ int s[SCB];
    int i = blockIdx.x * SCB + threadIdx.x;
    int v = (i < N_NODES_C) ? cnt[i] : 0;
    s[threadIdx.x] = v;
    __syncthreads();
    for (int o = 1; o < SCB; o <<= 1) {
        int a = (threadIdx.x >= o) ? s[threadIdx.x - o] : 0;
        __syncthreads();
        s[threadIdx.x] += a;
        __syncthreads();
    }
    if (i < N_NODES_C) wpos[i] = bsum[blockIdx.x] + s[threadIdx.x] - v;
}

// ---------------------------------------------------------------------------
// Reorder into row-grouped packed int2: w0 = col | rowLow14<<18,
// w1 = rowHigh4 | val_fp16<<16
// ---------------------------------------------------------------------------
__global__ void reorder_kernel(const int* __restrict__ rows,
                               const int* __restrict__ cols,
                               const float* __restrict__ vals,
                               int* __restrict__ wpos,
                               int2* __restrict__ epack) {
    int e = blockIdx.x * blockDim.x + threadIdx.x;
    if (e >= NNZ_C) return;
    int r = rows[e];
    int p = atomicAdd(&wpos[r], 1);
    unsigned short hv = __half_as_ushort(__float2half_rn(vals[e]));
    int w0 = cols[e] | ((r & 0x3FFF) << 18);
    int w1 = (r >> 14) | ((int)hv << 16);
    epack[p] = make_int2(w0, w1);
}

// ---------------------------------------------------------------------------
// Segmented SpMM over row-sorted packed edges, fp16 gather (best config)
// ---------------------------------------------------------------------------
#define EPS_C 16
#define EPB_C 256

__device__ __forceinline__ void red_v4(float4* dst, float4 a) {
    asm volatile("red.global.add.v4.f32 [%0], {%1, %2, %3, %4};"
                 :: "l"(dst), "f"(a.x), "f"(a.y), "f"(a.z), "f"(a.w)
                 : "memory");
}

__global__ __launch_bounds__(256)
void seg_spmm_h_kernel(const int2* __restrict__ epack,
                       const uint2* __restrict__ egoh,
                       float4* __restrict__ side) {
    int tid  = threadIdx.x;
    int slot = tid >> 4;
    int lane = tid & 15;
    int half = (tid & 31) >= 16 ? 16 : 0;
    int e0 = blockIdx.x * EPB_C + slot * EPS_C;

    int2 ep = epack[e0 + lane];

    float4 acc = make_float4(0.f, 0.f, 0.f, 0.f);
    int cur = -1;

#pragma unroll
    for (int b = 0; b < 4; b++) {
        int rr[4]; float vv[4]; uint2 gh[4];
#pragma unroll
        for (int u = 0; u < 4; u++) {
            int src = half + b * 4 + u;
            int w0 = __shfl_sync(0xffffffffu, ep.x, src);
            int w1 = __shfl_sync(0xffffffffu, ep.y, src);
            int c  = w0 & 0x3FFFF;
            rr[u]  = ((w0 >> 18) & 0x3FFF) | ((w1 & 0xF) << 14);
            vv[u]  = __half2float(__ushort_as_half((unsigned short)((unsigned)w1 >> 16)));
            gh[u]  = egoh[c * 16 + lane];
        }
#pragma unroll
        for (int u = 0; u < 4; u++) {
            if (rr[u] != cur) {
                if (cur >= 0) red_v4(&side[cur * 16 + lane], acc);
                acc = make_float4(0.f, 0.f, 0.f, 0.f);
                cur = rr[u];
            }
            __half2 h01 = *reinterpret_cast<__half2*>(&gh[u].x);
            __half2 h23 = *reinterpret_cast<__half2*>(&gh[u].y);
            float2 f01 = __half22float2(h01);
            float2 f23 = __half22float2(h23);
            acc.x = fmaf(vv[u], f01.x, acc.x);
            acc.y = fmaf(vv[u], f01.y, acc.y);
            acc.z = fmaf(vv[u], f23.x, acc.z);
            acc.w = fmaf(vv[u], f23.y, acc.w);
        }
    }
    if (cur >= 0)
        red_v4(&side[cur * 16 + lane], acc);
}

// ---------------------------------------------------------------------------
// Dense layer via tensor cores (HMMA fp16 in / fp32 accumulate):
// out = l2norm(leaky_relu(side@Wg + (ego*side)@Wb + bg + bb))
// ---------------------------------------------------------------------------
#define TM_C 64
#define KDIM_C 128
#define LDA_C 136
#define LDB_C 72

__global__ __launch_bounds__(128)
void dense_kernel(const float4* __restrict__ side,
                  const float4* __restrict__ ego,
                  const float4* __restrict__ Wg, const float* __restrict__ bg,
                  const float4* __restrict__ Wb, const float* __restrict__ bb,
                  float4* __restrict__ out, int numTiles) {
    extern __shared__ char smem[];
    __half* A   = (__half*)smem;                               // [64][136] halves
    __half* B   = (__half*)(smem + TM_C * LDA_C * 2);          // [128][72] halves
    float*  C   = (float*)(smem + TM_C * LDA_C * 2 + KDIM_C * LDB_C * 2);  // [64][64]
    float*  bsum = C + TM_C * D_C;                             // [64]

    int tid = threadIdx.x;
    int wid = tid >> 5;

#pragma unroll
    for (int i = 0; i < 16; i++) {
        int f = tid + i * 128;
        int k = f >> 4, c4 = f & 15;
        float4 w = (k < 64) ? Wg[k * 16 + c4] : Wb[(k - 64) * 16 + c4];
        __half2* dst = (__half2*)&B[k * LDB_C + c4 * 4];
        dst[0] = __floats2half2_rn(w.x, w.y);
        dst[1] = __floats2half2_rn(w.z, w.w);
    }
    if (tid < 64) bsum[tid] = bg[tid] + bb[tid];
    __syncthreads();

    for (int tile = blockIdx.x; tile < numTiles; tile += gridDim.x) {
        int row0 = tile * TM_C;

#pragma unroll
        for (int i = 0; i < 8; i++) {
            int f = tid + i * 128;
            int r = f >> 4, k4 = f & 15;
            float4 s  = make_float4(0.f, 0.f, 0.f, 0.f);
            float4 pr = make_float4(0.f, 0.f, 0.f, 0.f);
            int grow = row0 + r;
            if (grow < N_NODES_C) {
                s = side[grow * 16 + k4];
                float4 e = ego[grow * 16 + k4];
                pr = make_float4(s.x * e.x, s.y * e.y, s.z * e.z, s.w * e.w);
            }
            __half2* dS = (__half2*)&A[r * LDA_C + k4 * 4];
            dS[0] = __floats2half2_rn(s.x, s.y);
            dS[1] = __floats2half2_rn(s.z, s.w);
            __half2* dP = (__half2*)&A[r * LDA_C + 64 + k4 * 4];
            dP[0] = __floats2half2_rn(pr.x, pr.y);
            dP[1] = __floats2half2_rn(pr.z, pr.w);
        }
        __syncthreads();

        {
            wmma::fragment<wmma::accumulator, 16, 16, 16, float> c_frag[4];
#pragma unroll
            for (int n = 0; n < 4; n++) wmma::fill_fragment(c_frag[n], 0.f);
#pragma unroll
            for (int k = 0; k < KDIM_C / 16; k++) {
                wmma::fragment<wmma::matrix_a, 16, 16, 16, __half, wmma::row_major> a_frag;
                wmma::load_matrix_sync(a_frag, &A[(16 * wid) * LDA_C + k * 16], LDA_C);
#pragma unroll
                for (int n = 0; n < 4; n++) {
                    wmma::fragment<wmma::matrix_b, 16, 16, 16, __half, wmma::row_major> b_frag;
                    wmma::load_matrix_sync(b_frag, &B[(k * 16) * LDB_C + n * 16], LDB_C);
                    wmma::mma_sync(c_frag[n], a_frag, b_frag, c_frag[n]);
                }
            }
#pragma unroll
            for (int n = 0; n < 4; n++)
                wmma::store_matrix_sync(&C[(16 * wid) * D_C + n * 16], c_frag[n],
                                        D_C, wmma::mem_row_major);
        }
        __syncthreads();

        {
            int row = tid >> 1;
            int hs  = tid & 1;
            const float* Crow = C + row * D_C + hs * 32;
            const float* brow = bsum + hs * 32;
            float vbuf[32];
            float ss = 0.f;
#pragma unroll
            for (int j = 0; j < 32; j++) {
                float v = Crow[j] + brow[j];
                v = (v > 0.f) ? v : 0.2f * v;
                vbuf[j] = v;
                ss += v * v;
            }
            ss += __shfl_xor_sync(0xffffffffu, ss, 1);
            float scl = 1.0f / fmaxf(sqrtf(ss), 1e-12f);
            int grow = row0 + row;
            if (grow < N_NODES_C) {
#pragma unroll
                for (int j = 0; j < 8; j++)
                    out[grow * 16 + hs * 8 + j] =
                        make_float4(vbuf[4 * j] * scl, vbuf[4 * j + 1] * scl,
                                    vbuf[4 * j + 2] * scl, vbuf[4 * j + 3] * scl);
            }
        }
        __syncthreads();
    }
}

// ---------------------------------------------------------------------------
// gamma[b] = sum over 3 embeddings of dot(emb[u], emb[N_USERS+item])
// ---------------------------------------------------------------------------
__global__ void gamma_kernel(const float* __restrict__ x,
                             const int* __restrict__ users,
                             const int* __restrict__ items,
                             float* __restrict__ out) {
    int b = blockIdx.x * 8 + (threadIdx.x >> 5);
    if (b >= BATCH_C) return;
    int lane = threadIdx.x & 31;
    int u  = users[b];
    int it = N_USERS_C + items[b];
    long long ub = (long long)u * D_C, ib = (long long)it * D_C;
    float acc = 0.f;
    acc += x[ub + lane]      * x[ib + lane];
    acc += x[ub + 32 + lane] * x[ib + 32 + lane];
    acc += g_ego1[ub + lane]      * g_ego1[ib + lane];
    acc += g_ego1[ub + 32 + lane] * g_ego1[ib + 32 + lane];
    acc += g_ego2[ub + lane]      * g_ego2[ib + lane];
    acc += g_ego2[ub + 32 + lane] * g_ego2[ib + 32 + lane];
#pragma unroll
    for (int o = 16; o > 0; o >>= 1)
        acc += __shfl_xor_sync(0xffffffffu, acc, o);
    if (lane == 0) out[b] = acc;
}

// ---------------------------------------------------------------------------
extern "C" void kernel_launch(void* const* d_in, const int* in_sizes, int n_in,
                              void* d_out, int out_size) {
    const int*   rows = (const int*)d_in[0];
    const int*   cols = (const int*)d_in[1];
    const float* vals = (const float*)d_in[2];
    const float* x    = (const float*)d_in[3];

    const float *Wg0, *bg0, *Wb0, *bb0, *Wg1, *bg1, *Wb1, *bb1;
    const int *users, *items;
    if (in_sizes[4] == BATCH_C) {
        users = (const int*)d_in[4];
        items = (const int*)d_in[5];
        Wg0 = (const float*)d_in[6];  bg0 = (const float*)d_in[7];
        Wb0 = (const float*)d_in[8];  bb0 = (const float*)d_in[9];
        Wg1 = (const float*)d_in[10]; bg1 = (const float*)d_in[11];
        Wb1 = (const float*)d_in[12]; bb1 = (const float*)d_in[13];
    } else {
        Wg0 = (const float*)d_in[4];  bg0 = (const float*)d_in[5];
        Wb0 = (const float*)d_in[6];  bb0 = (const float*)d_in[7];
        Wg1 = (const float*)d_in[8];  bg1 = (const float*)d_in[9];
        Wb1 = (const float*)d_in[10]; bb1 = (const float*)d_in[11];
        users = (const int*)d_in[12];
        items = (const int*)d_in[13];
    }

    float *side, *ego1, *ego2;
    uint2 *egoh;
    int *cnt, *wpos, *bsum;
    int2 *epack;
    cudaGetSymbolAddress((void**)&side,  g_side);
    cudaGetSymbolAddress((void**)&ego1,  g_ego1);
    cudaGetSymbolAddress((void**)&ego2,  g_ego2);
    cudaGetSymbolAddress((void**)&egoh,  g_egoh);
    cudaGetSymbolAddress((void**)&cnt,   g_cnt);
    cudaGetSymbolAddress((void**)&wpos,  g_wpos);
    cudaGetSymbolAddress((void**)&bsum,  g_bsum);
    cudaGetSymbolAddress((void**)&epack, g_epack);

    int denseSmem = TM_C * LDA_C * 2 + KDIM_C * LDB_C * 2 + TM_C * D_C * 4 + 64 * 4;
    cudaFuncSetAttribute(dense_kernel, cudaFuncAttributeMaxDynamicSharedMemorySize, denseSmem);

    int numTiles   = (N_NODES_C + TM_C - 1) / TM_C;       // 2344
    int edgeBlocks = (NNZ_C + 255) / 256;                 // 9375
    int z4 = N_NODES_C * 16;
    int zeroBlocks = (z4 + 255) / 256;                    // 9375
    int spmmBlocks = NNZ_C / EPB_C;                       // 9375

    // 0-5: build row-grouped packed edge list (hierarchical scan)
    zero_cnt_kernel<<<NBLK_SCAN, SCB>>>(cnt);
    hist_kernel<<<edgeBlocks, 256>>>(rows, cnt);
    blocksum_kernel<<<NBLK_SCAN, SCB>>>(cnt, bsum);
    scan_bsum_kernel<<<1, 1024>>>(bsum);
    scan_final_kernel<<<NBLK_SCAN, SCB>>>(cnt, bsum, wpos);
    reorder_kernel<<<edgeBlocks, 256>>>(rows, cols, vals, wpos, epack);
    // Layer 1 (f2h_zero immediately before spmm1: warms egoh + side in L2)
    f2h_zero_kernel<<<zeroBlocks, 256>>>((const float4*)x, egoh, (float4*)side, z4);
    seg_spmm_h_kernel<<<spmmBlocks, 256>>>(epack, egoh, (float4*)side);
    dense_kernel<<<592, 128, denseSmem>>>((const float4*)side, (const float4*)x,
                                          (const float4*)Wg0, bg0,
                                          (const float4*)Wb0, bb0,
                                          (float4*)ego1, numTiles);
    // Layer 2 (same structure)
    f2h_zero_kernel<<<zeroBlocks, 256>>>((const float4*)ego1, egoh, (float4*)side, z4);
    seg_spmm_h_kernel<<<spmmBlocks, 256>>>(epack, egoh, (float4*)side);
    dense_kernel<<<592, 128, denseSmem>>>((const float4*)side, (const float4*)ego1,
                                          (const float4*)Wg1, bg1,
                                          (const float4*)Wb1, bb1,
                                          (float4*)ego2, numTiles);
    // Final BPR scores
    gamma_kernel<<<BATCH_C / 8, 256>>>(x, users, items, (float*)d_out);
}